// round 2
// baseline (speedup 1.0000x reference)
#include <cuda_runtime.h>
#include <cuda_bf16.h>

// UtilityInfrastructureBalancer: softmin Floyd-Warshall (512 steps, 512x512 f32)
// + fused loss epilogue. 128 persistent CTAs; each owns 4 consecutive rows of w
// in registers. Per step only row k crosses the chip (2KB via L2, flag-gated).

#define NN    512
#define RPB   4
#define NCTA  128
#define TPB   512

__device__ float g_rowbuf[NN * NN];     // row k (post step k-1), published by owner
__device__ int   g_flag[NN];            // publish flags
__device__ float g_part[NCTA * 4];      // per-CTA partials: cost, util, ent, mask

__device__ __forceinline__ int ld_acquire_gpu(const int* p) {
    int v;
    asm volatile("ld.global.acquire.gpu.b32 %0, [%1];" : "=r"(v) : "l"(p));
    return v;
}
__device__ __forceinline__ void st_release_gpu(int* p, int v) {
    asm volatile("st.global.release.gpu.b32 [%0], %1;" :: "l"(p), "r"(v));
}

__device__ __forceinline__ float softmin_g(float a, float b) {
    // -GAMMA * logaddexp(-a/G, -b/G), GAMMA=0.1
    // = min(a,b) - 0.1*log(1 + exp(-10*|a-b|))
    float m = fminf(a, b);
    float d = fabsf(a - b);
    return m - 0.1f * __logf(1.0f + __expf(-10.0f * d));
}

__global__ void __launch_bounds__(TPB) uib_init_kernel() {
    int t = threadIdx.x;
    if (t < NN) g_flag[t] = 0;
}

__global__ void __launch_bounds__(TPB, 1) uib_fw_kernel(
    const float* __restrict__ soft_adj,
    const float* __restrict__ orig_adj,
    const float* __restrict__ dist,
    const float* __restrict__ flow)
{
    const int t    = threadIdx.x;           // column index j
    const int c    = blockIdx.x;            // owns rows [4c, 4c+4)
    const int row0 = c << 2;
    const int wid  = t >> 5;
    const int lane = t & 31;

    __shared__ float col_sh[2][RPB];        // parity-buffered w[row0+r][k]
    __shared__ float red_sh[16][4];

    // init: w = (dist/(adj+1e-4)) * (1 - eye)
    float w[RPB];
#pragma unroll
    for (int r = 0; r < RPB; ++r) {
        const int i = row0 + r;
        const float a = soft_adj[i * NN + t];
        const float d = dist[i * NN + t];
        w[r] = (i == t) ? 0.0f : d / (a + 1e-4f);
    }

    // pre-step-0 row 0: computable from inputs by everyone
    float rk;
    {
        const float a = soft_adj[t];
        const float d = dist[t];
        rk = (t == 0) ? 0.0f : d / (a + 1e-4f);
    }

    for (int k = 0; k < NN; ++k) {
        const int par = k & 1;
        if (t == k) {
#pragma unroll
            for (int r = 0; r < RPB; ++r) col_sh[par][r] = w[r];
        }
        __syncthreads();
        float cs[RPB];
#pragma unroll
        for (int r = 0; r < RPB; ++r) cs[r] = col_sh[par][r];

        const int  kn       = k + 1;
        const bool own_next = (kn < NN) && ((kn >> 2) == c);

        // Early publish: update row k+1 first and release it so consumers'
        // end-of-step fetch finds the flag already set.
        if (own_next) {
            const int rn = kn & 3;
#pragma unroll
            for (int r = 0; r < RPB; ++r) {
                if (r == rn) {
                    const float wn = softmin_g(w[r], cs[r] + rk);
                    w[r] = wn;
                    g_rowbuf[kn * NN + t] = wn;
                }
            }
            __syncthreads();                 // all 512 column stores issued
            if (t == 0) {
                __threadfence();             // row visible at GPU scope
                st_release_gpu(&g_flag[kn], 1);
            }
        }

        // update remaining owned rows with pre-step snapshots (cs, rk)
#pragma unroll
        for (int r = 0; r < RPB; ++r) {
            if (!(own_next && ((kn & 3) == r)))
                w[r] = softmin_g(w[r], cs[r] + rk);
        }

        // fetch row k+1 for next step
        if (kn < NN) {
            if ((kn >> 2) == c) {
                const int rn = kn & 3;
#pragma unroll
                for (int r = 0; r < RPB; ++r)
                    if (r == rn) rk = w[r];
            } else {
                if (lane == 0) {
                    while (ld_acquire_gpu(&g_flag[kn]) == 0) __nanosleep(32);
                }
                __syncwarp();
                rk = __ldcg(&g_rowbuf[kn * NN + t]);
            }
        }
    }

    // ---- fused loss epilogue over owned rows ----
    float s_cost = 0.f, s_util = 0.f, s_ent = 0.f, s_mask = 0.f;
#pragma unroll
    for (int r = 0; r < RPB; ++r) {
        const int i   = row0 + r;
        const int idx = i * NN + t;
        const float sa = soft_adj[idx];
        const float oa = orig_adj[idx];
        const float di = dist[idx];
        const float fl = flow[idx];
        s_cost += sa * di;
        s_mask += sa * (1.0f - oa);
        const float io = (i == t) ? 1.0f : 0.0f;
        const float ee = sa * (io - sa);
        s_ent += ee * ee;

        const float sp   = w[r];
        const float rail = __expf(-0.005f * sp);       // UTILITY_SCALE*PRIORITY_RAIL
        const float base = __expf(-0.01f * di);        // UTILITY_SCALE
        const float ch   = rail / (rail + base);
        float ds = di - 0.5f * sp;                     // PRIORITY_RAIL
        ds = (ds > 0.0f) ? (ds + 1.0f) : __expf(ds);   // elu(x,1)+1
        if (i != t) s_util += fl * ch * ds;
    }

    // CTA reduction (deterministic)
#pragma unroll
    for (int o = 16; o > 0; o >>= 1) {
        s_cost += __shfl_down_sync(0xffffffffu, s_cost, o);
        s_util += __shfl_down_sync(0xffffffffu, s_util, o);
        s_ent  += __shfl_down_sync(0xffffffffu, s_ent,  o);
        s_mask += __shfl_down_sync(0xffffffffu, s_mask, o);
    }
    if (lane == 0) {
        red_sh[wid][0] = s_cost; red_sh[wid][1] = s_util;
        red_sh[wid][2] = s_ent;  red_sh[wid][3] = s_mask;
    }
    __syncthreads();
    if (t == 0) {
        float a = 0.f, b = 0.f, e = 0.f, m = 0.f;
#pragma unroll
        for (int q = 0; q < 16; ++q) {
            a += red_sh[q][0]; b += red_sh[q][1];
            e += red_sh[q][2]; m += red_sh[q][3];
        }
        g_part[c * 4 + 0] = a; g_part[c * 4 + 1] = b;
        g_part[c * 4 + 2] = e; g_part[c * 4 + 3] = m;
    }
}

__global__ void __launch_bounds__(128) uib_final_kernel(
    const int* __restrict__ epoch_ptr, float* __restrict__ out)
{
    const int t = threadIdx.x;
    float c = g_part[t * 4 + 0];
    float u = g_part[t * 4 + 1];
    float e = g_part[t * 4 + 2];
    float m = g_part[t * 4 + 3];
#pragma unroll
    for (int o = 16; o > 0; o >>= 1) {
        c += __shfl_down_sync(0xffffffffu, c, o);
        u += __shfl_down_sync(0xffffffffu, u, o);
        e += __shfl_down_sync(0xffffffffu, e, o);
        m += __shfl_down_sync(0xffffffffu, m, o);
    }
    __shared__ float sh[4][4];
    const int wid = t >> 5, lane = t & 31;
    if (lane == 0) { sh[wid][0] = c; sh[wid][1] = u; sh[wid][2] = e; sh[wid][3] = m; }
    __syncthreads();
    if (t == 0) {
        float C = sh[0][0] + sh[1][0] + sh[2][0] + sh[3][0];
        float U = sh[0][1] + sh[1][1] + sh[2][1] + sh[3][1];
        float E = sh[0][2] + sh[1][2] + sh[2][2] + sh[3][2];
        float M = sh[0][3] + sh[1][3] + sh[2][3] + sh[3][3];

        // epoch: robust read (int32 low word works for int32 AND little-endian
        // int64; fall back to float reinterpretation if implausible as int)
        int ep = epoch_ptr[0];
        if (ep > 100000 || ep < -100000) {
            float fep = __int_as_float(ep);
            ep = (int)fep;
        }
        const int idx = (ep >= 0 ? 1 : 0) + (ep >= 100 ? 1 : 0);
        const float lv[3] = {0.1f, 0.5f, 1.0f};
        out[0] = C + U + lv[idx] * E + lv[idx] * M;
    }
}

extern "C" void kernel_launch(void* const* d_in, const int* in_sizes, int n_in,
                              void* d_out, int out_size) {
    (void)in_sizes; (void)n_in; (void)out_size;
    const float* soft_adj = (const float*)d_in[0];
    const float* orig_adj = (const float*)d_in[1];
    const float* dist     = (const float*)d_in[2];
    const float* flow     = (const float*)d_in[3];
    const int*   epoch    = (const int*)d_in[4];
    float* out = (float*)d_out;

    uib_init_kernel<<<1, TPB>>>();
    uib_fw_kernel<<<NCTA, TPB>>>(soft_adj, orig_adj, dist, flow);
    uib_final_kernel<<<1, 128>>>(epoch, out);
}

// round 14
// speedup vs baseline: 1.0876x; 1.0876x over previous
#include <cuda_runtime.h>
#include <cuda_bf16.h>

// UtilityInfrastructureBalancer: softmin Floyd-Warshall (512 steps, 512x512 f32)
// + fused loss epilogue.
// 128 persistent CTAs; each owns 4 consecutive rows of w in registers. Per step
// only row k+1 crosses the chip (2KB via L2). Handoff protocol: PER-ELEMENT
// valid flags with release stores / acquire loads (the exact primitives from
// the round-2 PASSING kernel). Owner thread t stores its element (st.cg) then
// releases its flag; consumer t acquires its flag then loads its element.
// No CTA-wide fence, no sentinel values. The consumer issues its flag acquire
// EARLY (before the step's compute) so the L2 latency hides under the MUFU
// work; it only spins if the owner hasn't published yet.

#define NN    512
#define RPB   4
#define NCTA  128
#define TPB   512

__device__ float g_rowbuf[NN * NN];   // row k (state after step k-1)
__device__ int   g_vflag[NN * NN];    // per-element valid flags (0/1)
__device__ float g_part[NCTA * 4];    // per-CTA partials: cost, util, ent, mask

__device__ __forceinline__ int ld_acquire_gpu(const int* p) {
    int v;
    asm volatile("ld.global.acquire.gpu.b32 %0, [%1];" : "=r"(v) : "l"(p) : "memory");
    return v;
}
__device__ __forceinline__ void st_release_gpu(int* p, int v) {
    asm volatile("st.global.release.gpu.b32 [%0], %1;" :: "l"(p), "r"(v) : "memory");
}

__device__ __forceinline__ float softmin_g(float a, float b) {
    // -GAMMA*logaddexp(-a/G,-b/G), G=0.1  ==  min(a,b) - 0.1*log(1+exp(-10|a-b|))
    float m = fminf(a, b);
    float d = fabsf(a - b);
    return m - 0.1f * __logf(1.0f + __expf(-10.0f * d));
}

// Zero all valid flags (each is set exactly once per run by its owner thread).
__global__ void __launch_bounds__(256) uib_init_kernel() {
    const int i = blockIdx.x * blockDim.x + threadIdx.x;   // 65536 threads
    int4* p = reinterpret_cast<int4*>(g_vflag);            // int4 aligned (1MB array)
    p[i] = make_int4(0, 0, 0, 0);
}

__global__ void __launch_bounds__(TPB, 1) uib_fw_kernel(
    const float* __restrict__ soft_adj,
    const float* __restrict__ orig_adj,
    const float* __restrict__ dist,
    const float* __restrict__ flow)
{
    const int t    = threadIdx.x;           // column index j
    const int c    = blockIdx.x;            // owns rows [4c, 4c+4)
    const int row0 = c << 2;
    const int wid  = t >> 5;
    const int lane = t & 31;

    __shared__ float col_sh[2][RPB];        // parity-buffered w[row0+r][k]
    __shared__ float red_sh[16][4];

    // init: w = (dist/(adj+1e-4)) * (1 - eye)
    float w[RPB];
#pragma unroll
    for (int r = 0; r < RPB; ++r) {
        const int i = row0 + r;
        const float a = soft_adj[i * NN + t];
        const float d = dist[i * NN + t];
        w[r] = (i == t) ? 0.0f : d / (a + 1e-4f);
    }

    // pre-step-0 row 0 is computable from inputs by everyone
    float rk;
    {
        const float a = soft_adj[t];
        const float d = dist[t];
        rk = (t == 0) ? 0.0f : d / (a + 1e-4f);
    }

    for (int k = 0; k < NN; ++k) {
        const int par = k & 1;
        if (t == k) {
#pragma unroll
            for (int r = 0; r < RPB; ++r) col_sh[par][r] = w[r];
        }
        __syncthreads();
        float cs[RPB];
#pragma unroll
        for (int r = 0; r < RPB; ++r) cs[r] = col_sh[par][r];

        const int  kn       = k + 1;
        const bool have_kn  = (kn < NN);
        const bool own_next = have_kn && ((kn >> 2) == c);
        const int  slot     = kn * NN + t;

        float rk_next = 0.0f;

        if (own_next) {
            // Publish row k+1 first: element store + per-thread release flag.
            const int rn = kn & 3;
#pragma unroll
            for (int r = 0; r < RPB; ++r) {
                if (r == rn) {
                    const float wn = softmin_g(w[r], cs[r] + rk);
                    w[r] = wn;
                    __stcg(&g_rowbuf[slot], wn);
                    st_release_gpu(&g_vflag[slot], 1);
                    rk_next = wn;
                }
            }
            // remaining owned rows with pre-step snapshots
#pragma unroll
            for (int r = 0; r < RPB; ++r) {
                if (r != (kn & 3))
                    w[r] = softmin_g(w[r], cs[r] + rk);
            }
        } else {
            // Early acquire of next row's flag: latency hides under compute.
            int f_early = 0;
            if (have_kn) f_early = ld_acquire_gpu(&g_vflag[slot]);

#pragma unroll
            for (int r = 0; r < RPB; ++r)
                w[r] = softmin_g(w[r], cs[r] + rk);

            if (have_kn) {
                if (!f_early) {
                    while (ld_acquire_gpu(&g_vflag[slot]) == 0) { }
                }
                rk_next = __ldcg(&g_rowbuf[slot]);   // valid: acquire precedes
            }
        }
        rk = rk_next;
    }

    // ---- fused loss epilogue over owned rows ----
    float s_cost = 0.f, s_util = 0.f, s_ent = 0.f, s_mask = 0.f;
#pragma unroll
    for (int r = 0; r < RPB; ++r) {
        const int i   = row0 + r;
        const int idx = i * NN + t;
        const float sa = soft_adj[idx];
        const float oa = orig_adj[idx];
        const float di = dist[idx];
        const float fl = flow[idx];
        s_cost += sa * di;
        s_mask += sa * (1.0f - oa);
        const float io = (i == t) ? 1.0f : 0.0f;
        const float ee = sa * (io - sa);
        s_ent += ee * ee;

        const float sp   = w[r];
        const float rail = __expf(-0.005f * sp);       // UTILITY_SCALE*PRIORITY_RAIL
        const float base = __expf(-0.01f * di);        // UTILITY_SCALE
        const float ch   = rail / (rail + base);
        float ds = di - 0.5f * sp;                     // PRIORITY_RAIL
        ds = (ds > 0.0f) ? (ds + 1.0f) : __expf(ds);   // elu(x,1)+1
        if (i != t) s_util += fl * ch * ds;
    }

    // CTA reduction (deterministic)
#pragma unroll
    for (int o = 16; o > 0; o >>= 1) {
        s_cost += __shfl_down_sync(0xffffffffu, s_cost, o);
        s_util += __shfl_down_sync(0xffffffffu, s_util, o);
        s_ent  += __shfl_down_sync(0xffffffffu, s_ent,  o);
        s_mask += __shfl_down_sync(0xffffffffu, s_mask, o);
    }
    if (lane == 0) {
        red_sh[wid][0] = s_cost; red_sh[wid][1] = s_util;
        red_sh[wid][2] = s_ent;  red_sh[wid][3] = s_mask;
    }
    __syncthreads();
    if (t == 0) {
        float a = 0.f, b = 0.f, e = 0.f, m = 0.f;
#pragma unroll
        for (int q = 0; q < 16; ++q) {
            a += red_sh[q][0]; b += red_sh[q][1];
            e += red_sh[q][2]; m += red_sh[q][3];
        }
        g_part[c * 4 + 0] = a; g_part[c * 4 + 1] = b;
        g_part[c * 4 + 2] = e; g_part[c * 4 + 3] = m;
    }
}

__global__ void __launch_bounds__(128) uib_final_kernel(
    const int* __restrict__ epoch_ptr, float* __restrict__ out)
{
    const int t = threadIdx.x;
    float c = g_part[t * 4 + 0];
    float u = g_part[t * 4 + 1];
    float e = g_part[t * 4 + 2];
    float m = g_part[t * 4 + 3];
#pragma unroll
    for (int o = 16; o > 0; o >>= 1) {
        c += __shfl_down_sync(0xffffffffu, c, o);
        u += __shfl_down_sync(0xffffffffu, u, o);
        e += __shfl_down_sync(0xffffffffu, e, o);
        m += __shfl_down_sync(0xffffffffu, m, o);
    }
    __shared__ float sh[4][4];
    const int wid = t >> 5, lane = t & 31;
    if (lane == 0) { sh[wid][0] = c; sh[wid][1] = u; sh[wid][2] = e; sh[wid][3] = m; }
    __syncthreads();
    if (t == 0) {
        float C = sh[0][0] + sh[1][0] + sh[2][0] + sh[3][0];
        float U = sh[0][1] + sh[1][1] + sh[2][1] + sh[3][1];
        float E = sh[0][2] + sh[1][2] + sh[2][2] + sh[3][2];
        float M = sh[0][3] + sh[1][3] + sh[2][3] + sh[3][3];

        int ep = epoch_ptr[0];
        if (ep > 100000 || ep < -100000) {
            float fep = __int_as_float(ep);
            ep = (int)fep;
        }
        const int idx = (ep >= 0 ? 1 : 0) + (ep >= 100 ? 1 : 0);
        const float lv[3] = {0.1f, 0.5f, 1.0f};
        out[0] = C + U + lv[idx] * E + lv[idx] * M;
    }
}

extern "C" void kernel_launch(void* const* d_in, const int* in_sizes, int n_in,
                              void* d_out, int out_size) {
    (void)in_sizes; (void)n_in; (void)out_size;
    const float* soft_adj = (const float*)d_in[0];
    const float* orig_adj = (const float*)d_in[1];
    const float* dist     = (const float*)d_in[2];
    const float* flow     = (const float*)d_in[3];
    const int*   epoch    = (const int*)d_in[4];
    float* out = (float*)d_out;

    uib_init_kernel<<<256, 256>>>();
    uib_fw_kernel<<<NCTA, TPB>>>(soft_adj, orig_adj, dist, flow);
    uib_final_kernel<<<1, 128>>>(epoch, out);
}

// round 16
// speedup vs baseline: 2.1236x; 1.9525x over previous
#include <cuda_runtime.h>
#include <cuda_bf16.h>

// UtilityInfrastructureBalancer: BLOCKED softmin Floyd-Warshall (32 phases of
// B=16 steps) + fused loss epilogue.
//
// Reference: for k: w = softmin(w, w[:,k] + w[k,:]) with pre-step snapshots.
// Blocked exact reformulation: per phase, compute snapshot vectors
//   r_k[j] = w^(k-1)[k][j],  c_k[i] = w^(k-1)[i][k]   for k in the block,
// via a triangular recurrence (they depend only on block rows/cols + the 16x16
// diagonal block), then EVERY element applies the 16 updates in order from
// registers: w <- softmin(w, c_k[i] + r_k[j]).  This needs only ONE global
// barrier per 16 steps instead of a chip-wide handoff per step.
//
// 128 persistent CTAs x 512 threads; CTA c owns rows [4c,4c+4) in registers.
// Synchronization: stores + __threadfence + atomicAdd counters, acquire-load
// spins (the exact primitive set from the PASSING round-2/14 kernels).

#define NN    512
#define BB    16
#define NPH   (NN / BB)     // 32
#define RPB   4
#define NCTA  128
#define TPB   512

__device__ float g_brow[2][BB * NN];   // block rows w^(kb-1)[kb+m][j], parity p&1
__device__ float g_srow[2][BB * NN];   // row snapshots r_m[j], parity p&1
__device__ int   g_rowready;           // +4 per phase (block-row owners)
__device__ int   g_snapready;          // +128 per phase (all CTAs)
__device__ float g_part[NCTA * 4];     // per-CTA partials

__device__ __forceinline__ int ld_acquire_gpu(const int* p) {
    int v;
    asm volatile("ld.global.acquire.gpu.b32 %0, [%1];" : "=r"(v) : "l"(p) : "memory");
    return v;
}

__device__ __forceinline__ float softmin_g(float a, float b) {
    // -GAMMA*logaddexp(-a/G,-b/G), G=0.1  ==  min(a,b) - 0.1*log(1+exp(-10|a-b|))
    float m = fminf(a, b);
    float d = fabsf(a - b);
    return m - 0.1f * __logf(1.0f + __expf(-10.0f * d));
}

__global__ void __launch_bounds__(32) uib_init_kernel() {
    if (threadIdx.x == 0) { g_rowready = 0; g_snapready = 0; }
}

__global__ void __launch_bounds__(TPB, 1) uib_fw_kernel(
    const float* __restrict__ soft_adj,
    const float* __restrict__ orig_adj,
    const float* __restrict__ dist,
    const float* __restrict__ flow)
{
    const int t    = threadIdx.x;          // column index j
    const int c    = blockIdx.x;           // owns rows [4c, 4c+4)
    const int row0 = c << 2;
    const int wid  = t >> 5;
    const int lane = t & 31;

    __shared__ float rs_sh[BB][BB];        // rs_sh[m][k] = r_m[kb+k]
    __shared__ float cs_sh[BB][BB];        // cs_sh[m][k] = c_m[kb+k]
    __shared__ float cinit_sh[RPB][BB];    // phase-start w[i][kb+k] for own rows
    __shared__ float c_sh[RPB][BB];        // c snapshots for own rows
    __shared__ float red_sh[16][4];

    // init: w = (dist/(adj+1e-4)) * (1 - eye)
    float w[RPB];
#pragma unroll
    for (int r = 0; r < RPB; ++r) {
        const int i = row0 + r;
        const float a = soft_adj[i * NN + t];
        const float d = dist[i * NN + t];
        w[r] = (i == t) ? 0.0f : d / (a + 1e-4f);
    }

    // initial block-row publish (phase 0 rows, owners = CTAs 0..3)
    if (c < 4) {
#pragma unroll
        for (int r = 0; r < RPB; ++r)
            __stcg(&g_brow[0][(row0 + r) * NN + t], w[r]);
    }
    __threadfence();
    __syncthreads();
    if (c < 4 && t == 0) atomicAdd(&g_rowready, 1);

    for (int p = 0; p < NPH; ++p) {
        const int kb  = p * BB;
        const int par = p & 1;

        // capture phase-start column-inits for own rows (w[i][kb..kb+16))
        if (t >= kb && t < kb + BB) {
#pragma unroll
            for (int r = 0; r < RPB; ++r)
                cinit_sh[r][t - kb] = w[r];
        }

        // wait for this phase's block rows
        if (t == 0) { while (ld_acquire_gpu(&g_rowready) < 4 * (p + 1)) {} }
        __syncthreads();

        // ---- 16x16 diagonal-block triangular (threads 0..255) ----
        const int a = t >> 4, b = t & 15;
        float D = 0.0f;
        if (t < 256) D = __ldcg(&g_brow[par][a * NN + kb + b]);
        for (int m = 0; m < BB; ++m) {
            if (t < 256) {
                if (a == m) rs_sh[m][b] = D;   // pre-round row m
                if (b == m) cs_sh[m][a] = D;   // pre-round col m
            }
            __syncthreads();
            if (t < 256) D = softmin_g(D, cs_sh[m][a] + rs_sh[m][b]);
        }
        __syncthreads();

        // ---- slice triangulars: rows (threads 0..63), cols (64..127) ----
        const int kk = t & 15;
        float RV = 0.0f, CV = 0.0f;
        if (t < 64) {
            const int jl = t >> 4;                         // own column 4c+jl
            RV = __ldcg(&g_brow[par][kk * NN + (c * 4 + jl)]);
        } else if (t < 128) {
            const int r = (t - 64) >> 4;                   // own row 4c+r
            CV = cinit_sh[r][kk];
        }
#pragma unroll
        for (int m = 0; m < BB - 1; ++m) {
            const float RVm = __shfl_sync(0xffffffffu, RV, m, 16);
            const float CVm = __shfl_sync(0xffffffffu, CV, m, 16);
            if (t < 64) {
                if (kk > m) RV = softmin_g(RV, cs_sh[m][kk] + RVm);
            } else if (t < 128) {
                if (kk > m) CV = softmin_g(CV, CVm + rs_sh[m][kk]);
            }
        }
        if (t < 64) {
            const int jl = t >> 4;
            __stcg(&g_srow[par][kk * NN + c * 4 + jl], RV);
        } else if (t < 128) {
            const int r = (t - 64) >> 4;
            c_sh[r][kk] = CV;
        }
        __threadfence();
        __syncthreads();
        if (t == 0) atomicAdd(&g_snapready, 1);

        // ---- full grid barrier: all row-snapshot slices published ----
        if (t == 0) { while (ld_acquire_gpu(&g_snapready) < NCTA * (p + 1)) {} }
        __syncthreads();

        // ---- load r snapshots for own column, then interior sweep ----
        float rr[BB];
#pragma unroll
        for (int m = 0; m < BB; ++m)
            rr[m] = __ldcg(&g_srow[par][m * NN + t]);

#pragma unroll
        for (int m = 0; m < BB; ++m) {
#pragma unroll
            for (int r = 0; r < RPB; ++r)
                w[r] = softmin_g(w[r], c_sh[r][m] + rr[m]);
        }

        // ---- publish next phase's block rows (owners of block p+1) ----
        if (p + 1 < NPH && (c >> 2) == p + 1) {
#pragma unroll
            for (int r = 0; r < RPB; ++r)
                __stcg(&g_brow[(p + 1) & 1][(row0 + r - (p + 1) * BB) * NN + t], w[r]);
        }
        __threadfence();
        __syncthreads();
        if (p + 1 < NPH && (c >> 2) == p + 1 && t == 0)
            atomicAdd(&g_rowready, 1);
    }

    // ---- fused loss epilogue over owned rows (identical to passing R14) ----
    float s_cost = 0.f, s_util = 0.f, s_ent = 0.f, s_mask = 0.f;
#pragma unroll
    for (int r = 0; r < RPB; ++r) {
        const int i   = row0 + r;
        const int idx = i * NN + t;
        const float sa = soft_adj[idx];
        const float oa = orig_adj[idx];
        const float di = dist[idx];
        const float fl = flow[idx];
        s_cost += sa * di;
        s_mask += sa * (1.0f - oa);
        const float io = (i == t) ? 1.0f : 0.0f;
        const float ee = sa * (io - sa);
        s_ent += ee * ee;

        const float sp   = w[r];
        const float rail = __expf(-0.005f * sp);       // UTILITY_SCALE*PRIORITY_RAIL
        const float base = __expf(-0.01f * di);        // UTILITY_SCALE
        const float ch   = rail / (rail + base);
        float ds = di - 0.5f * sp;                     // PRIORITY_RAIL
        ds = (ds > 0.0f) ? (ds + 1.0f) : __expf(ds);   // elu(x,1)+1
        if (i != t) s_util += fl * ch * ds;
    }

#pragma unroll
    for (int o = 16; o > 0; o >>= 1) {
        s_cost += __shfl_down_sync(0xffffffffu, s_cost, o);
        s_util += __shfl_down_sync(0xffffffffu, s_util, o);
        s_ent  += __shfl_down_sync(0xffffffffu, s_ent,  o);
        s_mask += __shfl_down_sync(0xffffffffu, s_mask, o);
    }
    if (lane == 0) {
        red_sh[wid][0] = s_cost; red_sh[wid][1] = s_util;
        red_sh[wid][2] = s_ent;  red_sh[wid][3] = s_mask;
    }
    __syncthreads();
    if (t == 0) {
        float aa = 0.f, bb = 0.f, ee = 0.f, mm = 0.f;
#pragma unroll
        for (int q = 0; q < 16; ++q) {
            aa += red_sh[q][0]; bb += red_sh[q][1];
            ee += red_sh[q][2]; mm += red_sh[q][3];
        }
        g_part[c * 4 + 0] = aa; g_part[c * 4 + 1] = bb;
        g_part[c * 4 + 2] = ee; g_part[c * 4 + 3] = mm;
    }
}

__global__ void __launch_bounds__(128) uib_final_kernel(
    const int* __restrict__ epoch_ptr, float* __restrict__ out)
{
    const int t = threadIdx.x;
    float c = g_part[t * 4 + 0];
    float u = g_part[t * 4 + 1];
    float e = g_part[t * 4 + 2];
    float m = g_part[t * 4 + 3];
#pragma unroll
    for (int o = 16; o > 0; o >>= 1) {
        c += __shfl_down_sync(0xffffffffu, c, o);
        u += __shfl_down_sync(0xffffffffu, u, o);
        e += __shfl_down_sync(0xffffffffu, e, o);
        m += __shfl_down_sync(0xffffffffu, m, o);
    }
    __shared__ float sh[4][4];
    const int wid = t >> 5, lane = t & 31;
    if (lane == 0) { sh[wid][0] = c; sh[wid][1] = u; sh[wid][2] = e; sh[wid][3] = m; }
    __syncthreads();
    if (t == 0) {
        float C = sh[0][0] + sh[1][0] + sh[2][0] + sh[3][0];
        float U = sh[0][1] + sh[1][1] + sh[2][1] + sh[3][1];
        float E = sh[0][2] + sh[1][2] + sh[2][2] + sh[3][2];
        float M = sh[0][3] + sh[1][3] + sh[2][3] + sh[3][3];

        int ep = epoch_ptr[0];
        if (ep > 100000 || ep < -100000) {
            float fep = __int_as_float(ep);
            ep = (int)fep;
        }
        const int idx = (ep >= 0 ? 1 : 0) + (ep >= 100 ? 1 : 0);
        const float lv[3] = {0.1f, 0.5f, 1.0f};
        out[0] = C + U + lv[idx] * E + lv[idx] * M;
    }
}

extern "C" void kernel_launch(void* const* d_in, const int* in_sizes, int n_in,
                              void* d_out, int out_size) {
    (void)in_sizes; (void)n_in; (void)out_size;
    const float* soft_adj = (const float*)d_in[0];
    const float* orig_adj = (const float*)d_in[1];
    const float* dist     = (const float*)d_in[2];
    const float* flow     = (const float*)d_in[3];
    const int*   epoch    = (const int*)d_in[4];
    float* out = (float*)d_out;

    uib_init_kernel<<<1, 32>>>();
    uib_fw_kernel<<<NCTA, TPB>>>(soft_adj, orig_adj, dist, flow);
    uib_final_kernel<<<1, 128>>>(epoch, out);
}

// round 17
// speedup vs baseline: 2.4153x; 1.1374x over previous
#include <cuda_runtime.h>
#include <cuda_bf16.h>

// UtilityInfrastructureBalancer: BLOCKED softmin Floyd-Warshall, B=32 (16
// phases of 32 steps) + fused loss epilogue.
//
// Exact blocked reformulation of: for k: w = softmin(w, w[:,k] + w[k,:]) with
// pre-step snapshots. Per phase: owners publish the 32 block rows; every CTA
// redundantly solves the 32x32 diagonal triangular (giving the row/col
// snapshot restrictions rs/cs); each CTA computes the r-snapshot slices for
// its own 4 columns and the c-snapshots for its own 4 rows (warp-wide shuffle
// triangulars); one grid barrier; then a register-resident interior sweep of
// 32 ordered softmin updates. Two grid sync points per 32 steps (vs per step).
//
// 128 persistent CTAs x 512 threads; CTA c owns rows [4c,4c+4) in registers.
// Sync primitives: st.cg + __threadfence + atomicAdd counter, acquire-load
// spin — the exact set from the passing R14/R16 kernels.

#define NN    512
#define BB    32
#define NPH   (NN / BB)     // 16
#define RPB   4
#define NCTA  128
#define TPB   512

__device__ float g_brow[2][BB * NN];   // block rows at phase start, parity p&1
__device__ float g_srow[2][BB * NN];   // row snapshots r_m[j], parity p&1
__device__ int   g_rowready;           // +8 per phase (block-row owner CTAs)
__device__ int   g_snapready;          // +128 per phase (all CTAs)
__device__ float g_part[NCTA * 4];     // per-CTA partials

__device__ __forceinline__ int ld_acquire_gpu(const int* p) {
    int v;
    asm volatile("ld.global.acquire.gpu.b32 %0, [%1];" : "=r"(v) : "l"(p) : "memory");
    return v;
}

__device__ __forceinline__ float softmin_g(float a, float b) {
    // -0.1*logaddexp(-10a,-10b) = min(a,b) - 0.1*ln2*log2(1 + 2^(-10/ln2*|a-b|))
    float m = fminf(a, b);
    float d = fabsf(a - b);
    float e = exp2f(-14.426950408889634f * d);     // EX2
    return m - 0.069314718055994531f * __log2f(1.0f + e);  // LG2 + FFMA
}

__global__ void __launch_bounds__(32) uib_init_kernel() {
    if (threadIdx.x == 0) { g_rowready = 0; g_snapready = 0; }
}

__global__ void __launch_bounds__(TPB, 1) uib_fw_kernel(
    const float* __restrict__ soft_adj,
    const float* __restrict__ orig_adj,
    const float* __restrict__ dist,
    const float* __restrict__ flow)
{
    const int t    = threadIdx.x;          // column index j
    const int c    = blockIdx.x;           // owns rows [4c, 4c+4)
    const int row0 = c << 2;
    const int wid  = t >> 5;
    const int lane = t & 31;

    __shared__ float rs_sh[BB][BB];        // rs_sh[m][k] = r_m[kb+k] (pre-round m)
    __shared__ float cs_sh[BB][BB];        // cs_sh[m][k] = c_m[kb+k]
    __shared__ float cinit_sh[RPB][BB];    // phase-start w[i][kb+k], own rows
    __shared__ float c_sh[RPB][BB];        // c snapshots for own rows
    __shared__ float red_sh[16][4];

    // init: w = (dist/(adj+1e-4)) * (1 - eye)
    float w[RPB];
#pragma unroll
    for (int r = 0; r < RPB; ++r) {
        const int i = row0 + r;
        const float a = soft_adj[i * NN + t];
        const float d = dist[i * NN + t];
        w[r] = (i == t) ? 0.0f : d / (a + 1e-4f);
    }

    // initial block-row publish (block 0 rows; owners = CTAs 0..7)
    if (c < 8) {
#pragma unroll
        for (int r = 0; r < RPB; ++r)
            __stcg(&g_brow[0][(row0 + r) * NN + t], w[r]);
    }
    __threadfence();
    __syncthreads();
    if (c < 8 && t == 0) atomicAdd(&g_rowready, 1);

    for (int p = 0; p < NPH; ++p) {
        const int kb  = p * BB;
        const int par = p & 1;

        // capture phase-start column-inits for own rows (w[i][kb..kb+32))
        if (t >= kb && t < kb + BB) {
#pragma unroll
            for (int r = 0; r < RPB; ++r)
                cinit_sh[r][t - kb] = w[r];
        }

        // wait for this phase's block rows
        if (t == 0) { while (ld_acquire_gpu(&g_rowready) < 8 * (p + 1)) {} }
        __syncthreads();

        // ---- 32x32 diagonal triangular: 512 threads, 2 elements each ----
        const int a  = t >> 4;             // row 0..31
        const int b0 = t & 15;             // cols b0 and b0+16
        float D0 = __ldcg(&g_brow[par][a * NN + kb + b0]);
        float D1 = __ldcg(&g_brow[par][a * NN + kb + b0 + 16]);
        for (int m = 0; m < BB; ++m) {
            if (a == m)      { rs_sh[m][b0] = D0; rs_sh[m][b0 + 16] = D1; }
            if (b0 == m)       cs_sh[m][a] = D0;
            if (b0 + 16 == m)  cs_sh[m][a] = D1;
            __syncthreads();
            const float cm = cs_sh[m][a];
            D0 = softmin_g(D0, cm + rs_sh[m][b0]);
            D1 = softmin_g(D1, cm + rs_sh[m][b0 + 16]);
            __syncthreads();
        }

        // ---- slice triangulars: warps 0-3 rows (own cols), 4-7 cols (own rows)
        const int kk = lane;               // k index 0..31
        float RV = 0.0f, CV = 0.0f;
        if (wid < 4) {
            RV = __ldcg(&g_brow[par][kk * NN + (c * 4 + wid)]);
        } else if (wid < 8) {
            CV = cinit_sh[wid - 4][kk];
        }
#pragma unroll
        for (int m = 0; m < BB - 1; ++m) {
            const float RVm = __shfl_sync(0xffffffffu, RV, m);
            const float CVm = __shfl_sync(0xffffffffu, CV, m);
            if (wid < 4) {
                if (kk > m) RV = softmin_g(RV, cs_sh[m][kk] + RVm);
            } else if (wid < 8) {
                if (kk > m) CV = softmin_g(CV, CVm + rs_sh[m][kk]);
            }
        }
        if (wid < 4) {
            __stcg(&g_srow[par][kk * NN + c * 4 + wid], RV);
        } else if (wid < 8) {
            c_sh[wid - 4][kk] = CV;
        }
        __threadfence();
        __syncthreads();
        if (t == 0) atomicAdd(&g_snapready, 1);

        // ---- grid barrier: all row-snapshot slices published ----
        if (t == 0) { while (ld_acquire_gpu(&g_snapready) < NCTA * (p + 1)) {} }
        __syncthreads();

        // ---- load r snapshots for own column, then interior sweep ----
        float rr[BB];
#pragma unroll
        for (int m = 0; m < BB; ++m)
            rr[m] = __ldcg(&g_srow[par][m * NN + t]);

#pragma unroll
        for (int m = 0; m < BB; ++m) {
#pragma unroll
            for (int r = 0; r < RPB; ++r)
                w[r] = softmin_g(w[r], c_sh[r][m] + rr[m]);
        }

        // ---- publish next phase's block rows (owners of block p+1) ----
        if (p + 1 < NPH && (c >> 3) == p + 1) {
#pragma unroll
            for (int r = 0; r < RPB; ++r)
                __stcg(&g_brow[(p + 1) & 1][(row0 + r - (p + 1) * BB) * NN + t], w[r]);
        }
        __threadfence();
        __syncthreads();
        if (p + 1 < NPH && (c >> 3) == p + 1 && t == 0)
            atomicAdd(&g_rowready, 1);
    }

    // ---- fused loss epilogue over owned rows (identical to passing R16) ----
    float s_cost = 0.f, s_util = 0.f, s_ent = 0.f, s_mask = 0.f;
#pragma unroll
    for (int r = 0; r < RPB; ++r) {
        const int i   = row0 + r;
        const int idx = i * NN + t;
        const float sa = soft_adj[idx];
        const float oa = orig_adj[idx];
        const float di = dist[idx];
        const float fl = flow[idx];
        s_cost += sa * di;
        s_mask += sa * (1.0f - oa);
        const float io = (i == t) ? 1.0f : 0.0f;
        const float ee = sa * (io - sa);
        s_ent += ee * ee;

        const float sp   = w[r];
        const float rail = __expf(-0.005f * sp);       // UTILITY_SCALE*PRIORITY_RAIL
        const float base = __expf(-0.01f * di);        // UTILITY_SCALE
        const float ch   = rail / (rail + base);
        float ds = di - 0.5f * sp;                     // PRIORITY_RAIL
        ds = (ds > 0.0f) ? (ds + 1.0f) : __expf(ds);   // elu(x,1)+1
        if (i != t) s_util += fl * ch * ds;
    }

#pragma unroll
    for (int o = 16; o > 0; o >>= 1) {
        s_cost += __shfl_down_sync(0xffffffffu, s_cost, o);
        s_util += __shfl_down_sync(0xffffffffu, s_util, o);
        s_ent  += __shfl_down_sync(0xffffffffu, s_ent,  o);
        s_mask += __shfl_down_sync(0xffffffffu, s_mask, o);
    }
    if (lane == 0) {
        red_sh[wid][0] = s_cost; red_sh[wid][1] = s_util;
        red_sh[wid][2] = s_ent;  red_sh[wid][3] = s_mask;
    }
    __syncthreads();
    if (t == 0) {
        float aa = 0.f, bb = 0.f, ee = 0.f, mm = 0.f;
#pragma unroll
        for (int q = 0; q < 16; ++q) {
            aa += red_sh[q][0]; bb += red_sh[q][1];
            ee += red_sh[q][2]; mm += red_sh[q][3];
        }
        g_part[c * 4 + 0] = aa; g_part[c * 4 + 1] = bb;
        g_part[c * 4 + 2] = ee; g_part[c * 4 + 3] = mm;
    }
}

__global__ void __launch_bounds__(128) uib_final_kernel(
    const int* __restrict__ epoch_ptr, float* __restrict__ out)
{
    const int t = threadIdx.x;
    float c = g_part[t * 4 + 0];
    float u = g_part[t * 4 + 1];
    float e = g_part[t * 4 + 2];
    float m = g_part[t * 4 + 3];
#pragma unroll
    for (int o = 16; o > 0; o >>= 1) {
        c += __shfl_down_sync(0xffffffffu, c, o);
        u += __shfl_down_sync(0xffffffffu, u, o);
        e += __shfl_down_sync(0xffffffffu, e, o);
        m += __shfl_down_sync(0xffffffffu, m, o);
    }
    __shared__ float sh[4][4];
    const int wid = t >> 5, lane = t & 31;
    if (lane == 0) { sh[wid][0] = c; sh[wid][1] = u; sh[wid][2] = e; sh[wid][3] = m; }
    __syncthreads();
    if (t == 0) {
        float C = sh[0][0] + sh[1][0] + sh[2][0] + sh[3][0];
        float U = sh[0][1] + sh[1][1] + sh[2][1] + sh[3][1];
        float E = sh[0][2] + sh[1][2] + sh[2][2] + sh[3][2];
        float M = sh[0][3] + sh[1][3] + sh[2][3] + sh[3][3];

        int ep = epoch_ptr[0];
        if (ep > 100000 || ep < -100000) {
            float fep = __int_as_float(ep);
            ep = (int)fep;
        }
        const int idx = (ep >= 0 ? 1 : 0) + (ep >= 100 ? 1 : 0);
        const float lv[3] = {0.1f, 0.5f, 1.0f};
        out[0] = C + U + lv[idx] * E + lv[idx] * M;
    }
}

extern "C" void kernel_launch(void* const* d_in, const int* in_sizes, int n_in,
                              void* d_out, int out_size) {
    (void)in_sizes; (void)n_in; (void)out_size;
    const float* soft_adj = (const float*)d_in[0];
    const float* orig_adj = (const float*)d_in[1];
    const float* dist     = (const float*)d_in[2];
    const float* flow     = (const float*)d_in[3];
    const int*   epoch    = (const int*)d_in[4];
    float* out = (float*)d_out;

    uib_init_kernel<<<1, 32>>>();
    uib_fw_kernel<<<NCTA, TPB>>>(soft_adj, orig_adj, dist, flow);
    uib_final_kernel<<<1, 128>>>(epoch, out);
}